// round 5
// baseline (speedup 1.0000x reference)
#include <cuda_runtime.h>
#include <math.h>

#define NN 10000
#define EE 160000
#define IND 10
#define HID 256
#define EPAD 12
#define TT 5
#define ODIM 3

// ------------------------- static scratch (no allocation allowed) -----------
__device__ float  g_ea[EE * EPAD];      // normalized edge attrs, padded to 12
__device__ float  g_h[NN * HID];
__device__ float  g_xl[NN * HID];
__device__ float  g_xr[NN * HID];
__device__ float  g_out[NN * HID];
__device__ int    g_deg[NN];
__device__ int    g_rowptr[NN + 1];
__device__ int    g_writeptr[NN];
__device__ int    g_eid[EE];
__device__ int    g_src[EE];
__device__ double g_estats[18];         // [0:9) sum, [9:18) sumsq
__device__ double g_bstats[512];        // [0:256) sum, [256:512) sumsq
__device__ float  g_scale[HID];
__device__ float  g_shift[HID];

// ------------------------------- zeroing (no host-passed symbols!) ----------
__global__ void zero_pre_k() {
    int i = blockIdx.x * blockDim.x + threadIdx.x;
    if (i < 18) g_estats[i] = 0.0;
    if (i < NN) g_deg[i] = 0;
}
__global__ void zero_bstats_k() {
    int i = blockIdx.x * blockDim.x + threadIdx.x;
    if (i < 512) g_bstats[i] = 0.0;
}

// ------------------------- edge-attr normalization --------------------------
__global__ void ea_accum_k(const float* __restrict__ ea) {
    double s[9], q[9];
#pragma unroll
    for (int c = 0; c < 9; c++) { s[c] = 0.0; q[c] = 0.0; }
    int t0 = blockIdx.x * blockDim.x + threadIdx.x;
    int stride = gridDim.x * blockDim.x;
    for (int r = t0; r < EE; r += stride) {
#pragma unroll
        for (int c = 0; c < 9; c++) {
            double v = (double)ea[r * 9 + c];
            s[c] += v; q[c] += v * v;
        }
    }
#pragma unroll
    for (int c = 0; c < 9; c++) {
        for (int o = 16; o; o >>= 1) {
            s[c] += __shfl_down_sync(0xffffffffu, s[c], o);
            q[c] += __shfl_down_sync(0xffffffffu, q[c], o);
        }
    }
    if ((threadIdx.x & 31) == 0) {
#pragma unroll
        for (int c = 0; c < 9; c++) {
            atomicAdd(&g_estats[c], s[c]);
            atomicAdd(&g_estats[9 + c], q[c]);
        }
    }
}

__global__ void ea_norm_k(const float* __restrict__ ea) {
    __shared__ float smu[9], sinv[9];
    if (threadIdx.x < 9) {
        double mu  = g_estats[threadIdx.x] / (double)EE;
        double var = g_estats[9 + threadIdx.x] / (double)EE - mu * mu;
        if (var < 0.0) var = 0.0;
        float sd = sqrtf((float)var);
        smu[threadIdx.x]  = (float)mu;
        sinv[threadIdx.x] = 1.0f / (sd + 1e-8f);
    }
    __syncthreads();
    int r = blockIdx.x * blockDim.x + threadIdx.x;
    if (r >= EE) return;
#pragma unroll
    for (int c = 0; c < 9; c++)
        g_ea[r * EPAD + c] = (ea[r * 9 + c] - smu[c]) * sinv[c];
    g_ea[r * EPAD + 9]  = 0.f;
    g_ea[r * EPAD + 10] = 0.f;
    g_ea[r * EPAD + 11] = 0.f;
}

// ---------------------------------- lift ------------------------------------
__global__ void lift_k(const float* __restrict__ x, const float* __restrict__ W,
                       const float* __restrict__ b, float* __restrict__ h) {
    __shared__ float sx[IND];
    int row = blockIdx.x;
    if (threadIdx.x < IND) sx[threadIdx.x] = x[row * IND + threadIdx.x];
    __syncthreads();
    int c = threadIdx.x;
    float s = b[c];
#pragma unroll
    for (int k = 0; k < IND; k++) s += sx[k] * W[k * HID + c];
    h[row * HID + c] = fmaxf(s, 0.f);
}

// ------------------------------- CSR build ----------------------------------
__global__ void count_k(const int* __restrict__ ei) {
    int e = blockIdx.x * blockDim.x + threadIdx.x;
    if (e >= EE) return;
    atomicAdd(&g_deg[ei[EE + e]], 1);
}

__global__ void scan_k() {
    __shared__ int s[1024];
    __shared__ int carry;
    int tid = threadIdx.x;
    if (tid == 0) { carry = 0; g_rowptr[0] = 0; }
    __syncthreads();
    for (int base = 0; base < NN; base += 1024) {
        int i = base + tid;
        int v = (i < NN) ? g_deg[i] : 0;
        s[tid] = v;
        __syncthreads();
        for (int off = 1; off < 1024; off <<= 1) {
            int t = (tid >= off) ? s[tid - off] : 0;
            __syncthreads();
            s[tid] += t;
            __syncthreads();
        }
        int incl = s[tid] + carry;
        if (i < NN) { g_rowptr[i + 1] = incl; g_writeptr[i] = incl - v; }
        __syncthreads();
        if (tid == 0) carry += s[1023];
        __syncthreads();
    }
}

__global__ void scatter_k(const int* __restrict__ ei) {
    int e = blockIdx.x * blockDim.x + threadIdx.x;
    if (e >= EE) return;
    int d = ei[EE + e];
    int pos = atomicAdd(&g_writeptr[d], 1);
    g_eid[pos] = e;
    g_src[pos] = ei[e];
}

// ------------------------------ fp32 GEMM (M=NN, K=N=256) -------------------
__global__ void gemm_k256(const float* __restrict__ A, const float* __restrict__ B,
                          const float* __restrict__ bias, float* __restrict__ C) {
    __shared__ float As[16][64];
    __shared__ float Bs[16][64];
    int mbase = blockIdx.y << 6;
    int nbase = blockIdx.x << 6;
    int tid = threadIdx.x;
    int tr = tid >> 4, tc = tid & 15;
    float acc[4][4];
#pragma unroll
    for (int i = 0; i < 4; i++)
#pragma unroll
        for (int j = 0; j < 4; j++) acc[i][j] = 0.f;

    int lm  = tid >> 2;          // A row within tile (0..63)
    int lkq = (tid & 3) << 2;    // k quad (0,4,8,12)
    int lk  = tid >> 4;          // B k row (0..15)
    int ln  = (tid & 15) << 2;   // B n quad
    int arow = mbase + lm;
    bool aval = arow < NN;

    for (int kt = 0; kt < 256; kt += 16) {
        float4 av = aval ? *(const float4*)(A + arow * 256 + kt + lkq)
                         : make_float4(0.f, 0.f, 0.f, 0.f);
        As[lkq + 0][lm] = av.x; As[lkq + 1][lm] = av.y;
        As[lkq + 2][lm] = av.z; As[lkq + 3][lm] = av.w;
        *(float4*)&Bs[lk][ln] = *(const float4*)(B + (kt + lk) * 256 + nbase + ln);
        __syncthreads();
#pragma unroll
        for (int k = 0; k < 16; k++) {
            float4 a = *(const float4*)&As[k][tr << 2];
            float4 b = *(const float4*)&Bs[k][tc << 2];
            acc[0][0] += a.x * b.x; acc[0][1] += a.x * b.y; acc[0][2] += a.x * b.z; acc[0][3] += a.x * b.w;
            acc[1][0] += a.y * b.x; acc[1][1] += a.y * b.y; acc[1][2] += a.y * b.z; acc[1][3] += a.y * b.w;
            acc[2][0] += a.z * b.x; acc[2][1] += a.z * b.y; acc[2][2] += a.z * b.z; acc[2][3] += a.z * b.w;
            acc[3][0] += a.w * b.x; acc[3][1] += a.w * b.y; acc[3][2] += a.w * b.z; acc[3][3] += a.w * b.w;
        }
        __syncthreads();
    }
    float4 bv = *(const float4*)(bias + nbase + (tc << 2));
#pragma unroll
    for (int i = 0; i < 4; i++) {
        int row = mbase + (tr << 2) + i;
        if (row < NN) {
            float4 o;
            o.x = acc[i][0] + bv.x; o.y = acc[i][1] + bv.y;
            o.z = acc[i][2] + bv.z; o.w = acc[i][3] + bv.w;
            *(float4*)(C + row * 256 + nbase + (tc << 2)) = o;
        }
    }
}

// ------------------------ GATv2 edge pass (online softmax) ------------------
// 2 warps per node; warp half h covers channels [h*128, h*128+128), 4 ch/lane.
// Head group = 8 consecutive lanes (32 channels). We slice held in registers.
__global__ void gat_edge_k(const float* __restrict__ xl, const float* __restrict__ xr,
                           const float* __restrict__ We_t, const float* __restrict__ att_t,
                           const float* __restrict__ cbias, float* __restrict__ out) {
    int gw = (blockIdx.x * blockDim.x + threadIdx.x) >> 5;
    int lane = threadIdx.x & 31;
    if (gw >= NN * 2) return;
    int node = gw >> 1;
    int cb = ((gw & 1) << 7) + (lane << 2);

    float4 wk[9];
#pragma unroll
    for (int k = 0; k < 9; k++) wk[k] = *(const float4*)(We_t + k * HID + cb);
    float4 xr4 = *(const float4*)(xr + node * HID + cb);
    float4 at4 = *(const float4*)(att_t + cb);

    int beg = g_rowptr[node], end = g_rowptr[node + 1];
    float maxl = -INFINITY, denom = 0.f;
    float a0 = 0.f, a1 = 0.f, a2 = 0.f, a3 = 0.f;

    for (int pos = beg; pos < end; pos++) {
        int e = g_eid[pos];
        int s = g_src[pos];
        const float4* eap = (const float4*)(g_ea + e * EPAD);
        float4 e0 = eap[0], e1 = eap[1], e2 = eap[2];
        float4 x4 = *(const float4*)(xl + s * HID + cb);

        float xe0 = e0.x*wk[0].x + e0.y*wk[1].x + e0.z*wk[2].x + e0.w*wk[3].x
                  + e1.x*wk[4].x + e1.y*wk[5].x + e1.z*wk[6].x + e1.w*wk[7].x + e2.x*wk[8].x;
        float xe1 = e0.x*wk[0].y + e0.y*wk[1].y + e0.z*wk[2].y + e0.w*wk[3].y
                  + e1.x*wk[4].y + e1.y*wk[5].y + e1.z*wk[6].y + e1.w*wk[7].y + e2.x*wk[8].y;
        float xe2 = e0.x*wk[0].z + e0.y*wk[1].z + e0.z*wk[2].z + e0.w*wk[3].z
                  + e1.x*wk[4].z + e1.y*wk[5].z + e1.z*wk[6].z + e1.w*wk[7].z + e2.x*wk[8].z;
        float xe3 = e0.x*wk[0].w + e0.y*wk[1].w + e0.z*wk[2].w + e0.w*wk[3].w
                  + e1.x*wk[4].w + e1.y*wk[5].w + e1.z*wk[6].w + e1.w*wk[7].w + e2.x*wk[8].w;

        float v0 = x4.x + xr4.x + xe0; v0 = v0 > 0.f ? v0 : 0.2f * v0;
        float v1 = x4.y + xr4.y + xe1; v1 = v1 > 0.f ? v1 : 0.2f * v1;
        float v2 = x4.z + xr4.z + xe2; v2 = v2 > 0.f ? v2 : 0.2f * v2;
        float v3 = x4.w + xr4.w + xe3; v3 = v3 > 0.f ? v3 : 0.2f * v3;

        float part = v0 * at4.x + v1 * at4.y + v2 * at4.z + v3 * at4.w;
        part += __shfl_xor_sync(0xffffffffu, part, 1);
        part += __shfl_xor_sync(0xffffffffu, part, 2);
        part += __shfl_xor_sync(0xffffffffu, part, 4);

        float nm = fmaxf(maxl, part);
        float sc = __expf(maxl - nm);   // 0 on first edge (maxl = -inf)
        float z  = __expf(part - nm);
        denom = denom * sc + z;
        a0 = a0 * sc + z * x4.x;
        a1 = a1 * sc + z * x4.y;
        a2 = a2 * sc + z * x4.z;
        a3 = a3 * sc + z * x4.w;
        maxl = nm;
    }
    float inv = 1.f / (denom + 1e-16f);
    float4 o;
    o.x = a0 * inv + cbias[cb + 0];
    o.y = a1 * inv + cbias[cb + 1];
    o.z = a2 * inv + cbias[cb + 2];
    o.w = a3 * inv + cbias[cb + 3];
    *(float4*)(out + node * HID + cb) = o;
}

// --------------------------------- BatchNorm --------------------------------
__global__ void bn_accum_k(const float* __restrict__ a) {
    int c = threadIdx.x;
    double s = 0.0, q = 0.0;
    for (int r = blockIdx.x; r < NN; r += gridDim.x) {
        double v = (double)a[r * HID + c];
        s += v; q += v * v;
    }
    atomicAdd(&g_bstats[c], s);
    atomicAdd(&g_bstats[256 + c], q);
}

__global__ void bn_final_k(const float* __restrict__ gamma, const float* __restrict__ beta) {
    int c = threadIdx.x;
    double mu  = g_bstats[c] / (double)NN;
    double var = g_bstats[256 + c] / (double)NN - mu * mu;
    if (var < 0.0) var = 0.0;
    float sc = gamma[c] * rsqrtf((float)var + 1e-5f);
    g_scale[c] = sc;
    g_shift[c] = beta[c] - (float)mu * sc;
}

// mode 0: ELU, mode 1: ReLU
__global__ void bn_apply_k(const float* __restrict__ in, float* __restrict__ outp, int mode) {
    int i = blockIdx.x * blockDim.x + threadIdx.x;
    if (i >= NN * HID) return;
    int c = i & 255;
    float y = in[i] * g_scale[c] + g_shift[c];
    if (mode == 0) y = y > 0.f ? y : expm1f(y);
    else           y = fmaxf(y, 0.f);
    outp[i] = y;
}

// --------------------------- final 256x3 projection -------------------------
__global__ void proj3_k(const float* __restrict__ h, const float* __restrict__ W,
                        const float* __restrict__ b, float* __restrict__ out) {
    int gw = (blockIdx.x * blockDim.x + threadIdx.x) >> 5;
    int lane = threadIdx.x & 31;
    if (gw >= NN) return;
    const float* hp = h + gw * HID + lane * 8;
    float4 h0 = *(const float4*)hp;
    float4 h1 = *(const float4*)(hp + 4);
    float hv[8] = {h0.x, h0.y, h0.z, h0.w, h1.x, h1.y, h1.z, h1.w};
    float s0 = 0.f, s1 = 0.f, s2 = 0.f;
#pragma unroll
    for (int j = 0; j < 8; j++) {
        int c = lane * 8 + j;
        s0 += hv[j] * W[c * 3 + 0];
        s1 += hv[j] * W[c * 3 + 1];
        s2 += hv[j] * W[c * 3 + 2];
    }
    for (int o = 16; o; o >>= 1) {
        s0 += __shfl_down_sync(0xffffffffu, s0, o);
        s1 += __shfl_down_sync(0xffffffffu, s1, o);
        s2 += __shfl_down_sync(0xffffffffu, s2, o);
    }
    if (lane == 0) {
        out[gw * 3 + 0] = s0 + b[0];
        out[gw * 3 + 1] = s1 + b[1];
        out[gw * 3 + 2] = s2 + b[2];
    }
}

// --------------------------------- launcher ---------------------------------
extern "C" void kernel_launch(void* const* d_in, const int* in_sizes, int n_in,
                              void* d_out, int out_size) {
    const float* x         = (const float*)d_in[0];
    const float* edge_attr = (const float*)d_in[1];
    const int*   edge_idx  = (const int*)  d_in[2];
    const float* lift_W    = (const float*)d_in[3];
    const float* lift_b    = (const float*)d_in[4];
    const float* Wl        = (const float*)d_in[5];
    const float* bl        = (const float*)d_in[6];
    const float* Wr        = (const float*)d_in[7];
    const float* br        = (const float*)d_in[8];
    const float* We        = (const float*)d_in[9];
    const float* att       = (const float*)d_in[10];
    const float* conv_bias = (const float*)d_in[11];
    const float* bn_gamma  = (const float*)d_in[12];
    const float* bn_beta   = (const float*)d_in[13];
    const float* p1_W      = (const float*)d_in[14];
    const float* p1_b      = (const float*)d_in[15];
    const float* pbn1_g    = (const float*)d_in[16];
    const float* pbn1_b    = (const float*)d_in[17];
    const float* p2_W      = (const float*)d_in[18];
    const float* p2_b      = (const float*)d_in[19];
    const float* pbn2_g    = (const float*)d_in[20];
    const float* pbn2_b    = (const float*)d_in[21];
    const float* p3_W      = (const float*)d_in[22];
    const float* p3_b      = (const float*)d_in[23];
    float* outp = (float*)d_out;

    // IMPORTANT: __device__ symbols must be resolved to REAL device addresses
    // before being passed as kernel arguments. Host-code decay of the symbol
    // gives the host shadow address (silently wrong under ATS).
    float* p_h   = nullptr;  cudaGetSymbolAddress((void**)&p_h,   g_h);
    float* p_xl  = nullptr;  cudaGetSymbolAddress((void**)&p_xl,  g_xl);
    float* p_xr  = nullptr;  cudaGetSymbolAddress((void**)&p_xr,  g_xr);
    float* p_out = nullptr;  cudaGetSymbolAddress((void**)&p_out, g_out);

    const int EB = (EE + 255) / 256;          // 625
    dim3 ggrid(4, (NN + 63) / 64);            // 4 x 157

    // zero scratch that needs it
    zero_pre_k<<<(NN + 255) / 256, 256>>>();

    // edge-attr normalization
    ea_accum_k<<<64, 256>>>(edge_attr);
    ea_norm_k<<<EB, 256>>>(edge_attr);

    // lift
    lift_k<<<NN, 256>>>(x, lift_W, lift_b, p_h);

    // CSR by dst
    count_k<<<EB, 256>>>(edge_idx);
    scan_k<<<1, 1024>>>();
    scatter_k<<<EB, 256>>>(edge_idx);

    // T GATv2 layers
    for (int t = 0; t < TT; t++) {
        gemm_k256<<<ggrid, 256>>>(p_h, Wl + t * HID * HID, bl + t * HID, p_xl);
        gemm_k256<<<ggrid, 256>>>(p_h, Wr + t * HID * HID, br + t * HID, p_xr);
        gat_edge_k<<<(NN * 2 * 32 + 255) / 256, 256>>>(
            p_xl, p_xr, We + t * 9 * HID, att + t * HID, conv_bias + t * HID, p_out);
        zero_bstats_k<<<2, 256>>>();
        bn_accum_k<<<240, 256>>>(p_out);
        bn_final_k<<<1, 256>>>(bn_gamma + t * HID, bn_beta + t * HID);
        bn_apply_k<<<(NN * HID + 255) / 256, 256>>>(p_out, p_h, 0);
    }

    // projection MLP
    gemm_k256<<<ggrid, 256>>>(p_h, p1_W, p1_b, p_xl);
    zero_bstats_k<<<2, 256>>>();
    bn_accum_k<<<240, 256>>>(p_xl);
    bn_final_k<<<1, 256>>>(pbn1_g, pbn1_b);
    bn_apply_k<<<(NN * HID + 255) / 256, 256>>>(p_xl, p_xl, 1);

    gemm_k256<<<ggrid, 256>>>(p_xl, p2_W, p2_b, p_xr);
    zero_bstats_k<<<2, 256>>>();
    bn_accum_k<<<240, 256>>>(p_xr);
    bn_final_k<<<1, 256>>>(pbn2_g, pbn2_b);
    bn_apply_k<<<(NN * HID + 255) / 256, 256>>>(p_xr, p_xr, 1);

    proj3_k<<<(NN * 32 + 255) / 256, 256>>>(p_xr, p3_W, p3_b, outp);
}